// round 12
// baseline (speedup 1.0000x reference)
#include <cuda_runtime.h>
#include <cuda_bf16.h>
#include <math.h>

// ---------------------------------------------------------------------------
// GPT forward. Pre-split bf16x3 tensor-core GEMMs with cp.async pipeline.
// B=4, T=512, K=512, H=8, NB=4, VOCAB=32000. M = B*T = 2048 tokens.
//
// R11: 64x64 warp tiles (4 warps / 128 threads per 128x128 CTA tile) to halve
// SMEM fragment traffic per MMA (128 -> 85 B/MMA); crossbar was the binding
// pipe. Split-K skinny GEMMs, fused QKV, causal skip/truncate unchanged.
// ---------------------------------------------------------------------------

#define BATCH 4
#define SEQ   512
#define KD    512
#define HEADS 8
#define NBLK  4
#define VOCAB 32000
#define MTOK  (BATCH*SEQ)        // 2048
#define HK    (HEADS*KD)         // 4096
#define QKVN  (3*HK)             // 12288
#define FF    (4*KD)             // 2048
#define NBH   (BATCH*HEADS)      // 32

// fp32 scratch
__device__ float g_h  [MTOK*KD];
__device__ float g_att[NBH*SEQ*SEQ];      // scores; reused as split-K partials
__device__ float g_tmp[MTOK*KD];
// split bf16 scratch
__device__ __align__(256) __nv_bfloat16 g_hs_h[MTOK*KD],  g_hs_l[MTOK*KD];
__device__ __align__(256) __nv_bfloat16 g_wt_h[(size_t)VOCAB*KD], g_wt_l[(size_t)VOCAB*KD];
__device__ __align__(256) __nv_bfloat16 g_qkv_h[(size_t)MTOK*QKVN], g_qkv_l[(size_t)MTOK*QKVN];
__device__ __align__(256) __nv_bfloat16 g_vt_h[MTOK*HK],  g_vt_l[MTOK*HK];
__device__ __align__(256) __nv_bfloat16 g_as_h[NBH*SEQ*SEQ], g_as_l[NBH*SEQ*SEQ];
__device__ __align__(256) __nv_bfloat16 g_ys_h[MTOK*HK],  g_ys_l[MTOK*HK];
__device__ __align__(256) __nv_bfloat16 g_fs_h[MTOK*FF],  g_fs_l[MTOK*FF];

// ---------------------------------------------------------------------------
// helpers
// ---------------------------------------------------------------------------
__device__ __forceinline__ unsigned smem_u32(const void* p) {
    unsigned r;
    asm("{ .reg .u64 t; cvta.to.shared.u64 t, %1; cvt.u32.u64 %0, t; }"
        : "=r"(r) : "l"(p));
    return r;
}
__device__ __forceinline__ void cp16(unsigned dst, const void* src) {
    asm volatile("cp.async.cg.shared.global [%0], [%1], 16;" :: "r"(dst), "l"(src));
}
#define CP_COMMIT() asm volatile("cp.async.commit_group;" ::: "memory")
#define CP_WAIT1()  asm volatile("cp.async.wait_group 1;" ::: "memory")

__device__ __forceinline__ void ldsm4(unsigned addr, unsigned& r0, unsigned& r1,
                                      unsigned& r2, unsigned& r3) {
    asm volatile("ldmatrix.sync.aligned.m8n8.x4.shared.b16 {%0,%1,%2,%3}, [%4];"
                 : "=r"(r0), "=r"(r1), "=r"(r2), "=r"(r3) : "r"(addr));
}
__device__ __forceinline__ void ldsm2(unsigned addr, unsigned& r0, unsigned& r1) {
    asm volatile("ldmatrix.sync.aligned.m8n8.x2.shared.b16 {%0,%1}, [%2];"
                 : "=r"(r0), "=r"(r1) : "r"(addr));
}
__device__ __forceinline__ void mma16(float* c, const unsigned* a, const unsigned* b) {
    asm volatile(
        "mma.sync.aligned.m16n8k16.row.col.f32.bf16.bf16.f32 "
        "{%0,%1,%2,%3},{%4,%5,%6,%7},{%8,%9},{%0,%1,%2,%3};"
        : "+f"(c[0]), "+f"(c[1]), "+f"(c[2]), "+f"(c[3])
        : "r"(a[0]), "r"(a[1]), "r"(a[2]), "r"(a[3]), "r"(b[0]), "r"(b[1]));
}
__device__ __forceinline__ void splitw(float v, __nv_bfloat16* ph, __nv_bfloat16* pl) {
    __nv_bfloat16 hi = __float2bfloat16(v);
    *ph = hi;
    *pl = __float2bfloat16(v - __bfloat162float(hi));
}
__device__ __forceinline__ void split2(float a, float b,
                                       __nv_bfloat162& H, __nv_bfloat162& L) {
    __nv_bfloat16 ha = __float2bfloat16(a), hb = __float2bfloat16(b);
    H = __halves2bfloat162(ha, hb);
    L = __halves2bfloat162(__float2bfloat16(a - __bfloat162float(ha)),
                           __float2bfloat16(b - __bfloat162float(hb)));
}

// SMEM stage layout (uint32 units): [AH 2048 | AL 2048 | BH 2048 | BL 2048]
// Tile row = 16 uint32 (32 bf16 along k), swizzle col' = c ^ ((row&6)<<1).
#define ST_U32 8192
#define AH_OFF 0
#define AL_OFF 2048
#define BH_OFF 4096
#define BL_OFF 6144
#define NSTAGE 3
#define GEMM_SMEM (NSTAGE*ST_U32*4)   // 98304 bytes

// ---------------------------------------------------------------------------
// Pipelined split-bf16 GEMM. 128 threads, 4 warps, warp tile 64x64.
// causal: 0 none, 1 tile-skip (bx>by), 2 K-trunc to (by+1)*128.
// Batched / split-K via blockIdx.z with (aO,aI,bO,bI,cO,cI,zdiv) strides.
// ---------------------------------------------------------------------------
template<int EPI, int OUT>
__global__ __launch_bounds__(128, 2)
void gemm_ps(const __nv_bfloat16* __restrict__ Ah, const __nv_bfloat16* __restrict__ Al,
             const __nv_bfloat16* __restrict__ Bh, const __nv_bfloat16* __restrict__ Bl,
             const float* __restrict__ bias,
             float* __restrict__ C,
             __nv_bfloat16* __restrict__ Ch, __nv_bfloat16* __restrict__ Cl,
             int M, int N, int K, int lda, int ldb, int ldc,
             long aO, long aI, long bO, long bI, long cO, long cI, int zdiv,
             int causal)
{
    extern __shared__ unsigned sm[];
    const unsigned base32 = smem_u32(sm);

    const int bx = blockIdx.x, by = blockIdx.y;
    if (causal == 1 && bx > by) return;
    if (causal == 2) K = min(K, (by + 1) * 128);

    const int z  = blockIdx.z;
    const int zb = z / zdiv, zh = z - zb * zdiv;
    const size_t aoff = (size_t)zb * aO + (size_t)zh * aI;
    const size_t boff = (size_t)zb * bO + (size_t)zh * bI;
    const size_t coff = (size_t)zb * cO + (size_t)zh * cI;
    Ah += aoff; Al += aoff; Bh += boff; Bl += boff;

    const int tid  = threadIdx.x;
    const int lane = tid & 31;
    const int warp = tid >> 5;           // 0..3
    const int g    = lane >> 2;
    const int tc   = lane & 3;
    const int wm   = (warp >> 1) * 64;   // 2x2 warp grid, 64x64 tiles
    const int wn   = (warp & 1) * 64;

    // cp.async mapping: thread -> tile row (tid), 4 granules of 16B along k
    const int crow = tid;
    const __nv_bfloat16* pAh = Ah + (size_t)(by * 128 + crow) * lda;
    const __nv_bfloat16* pAl = Al + (size_t)(by * 128 + crow) * lda;
    const __nv_bfloat16* pBh = Bh + (size_t)(bx * 128 + crow) * ldb;
    const __nv_bfloat16* pBl = Bl + (size_t)(bx * 128 + crow) * ldb;
    const int csw = (crow & 6) << 1;
    int cs[4];
    #pragma unroll
    for (int j = 0; j < 4; j++)
        cs[j] = crow * 16 + ((4 * j) ^ csw);

    // ldmatrix source indices (uint32 units, region-relative)
    int idxA[4][2], idxB[8][2];
    {
        const int rowA = wm + (lane & 15);
        const int cgA0 = (lane >> 4) << 2;
        const int rowB = wn + (lane & 7);
        const int cgB0 = ((lane >> 3) & 1) << 2;
        #pragma unroll
        for (int mf = 0; mf < 4; mf++) {
            const int r = rowA + mf * 16;
            idxA[mf][0] = r * 16 + ((cgA0)     ^ ((r & 6) << 1));
            idxA[mf][1] = r * 16 + ((cgA0 + 8) ^ ((r & 6) << 1));
        }
        #pragma unroll
        for (int nf = 0; nf < 8; nf++) {
            const int r = rowB + nf * 8;
            idxB[nf][0] = r * 16 + ((cgB0)     ^ ((r & 6) << 1));
            idxB[nf][1] = r * 16 + ((cgB0 + 8) ^ ((r & 6) << 1));
        }
    }

    float acc[4][8][4];
    #pragma unroll
    for (int i = 0; i < 4; i++)
        #pragma unroll
        for (int j = 0; j < 8; j++)
            #pragma unroll
            for (int r = 0; r < 4; r++) acc[i][j][r] = 0.f;

    auto ISSUE = [&](int buf, int k0) {
        const unsigned sb = base32 + buf * (ST_U32 * 4);
        #pragma unroll
        for (int j = 0; j < 4; j++) {
            cp16(sb + (AH_OFF + cs[j]) * 4, pAh + k0 + j * 8);
            cp16(sb + (AL_OFF + cs[j]) * 4, pAl + k0 + j * 8);
            cp16(sb + (BH_OFF + cs[j]) * 4, pBh + k0 + j * 8);
            cp16(sb + (BL_OFF + cs[j]) * 4, pBl + k0 + j * 8);
        }
    };

    const int nc = K >> 5;

    ISSUE(0, 0);  CP_COMMIT();
    if (nc > 1) ISSUE(1, 32);
    CP_COMMIT();

    for (int i = 0; i < nc; i++) {
        CP_WAIT1();
        __syncthreads();

        if (i + 2 < nc) ISSUE((i + 2) % NSTAGE, (i + 2) * 32);
        CP_COMMIT();

        const unsigned stb = base32 + (i % NSTAGE) * (ST_U32 * 4);
        #pragma unroll
        for (int kpb = 0; kpb < 2; kpb++) {
            unsigned Bf[8][2], Mf[8][2];
            #pragma unroll
            for (int nf = 0; nf < 8; nf++) {
                ldsm2(stb + (BH_OFF + idxB[nf][kpb]) * 4, Bf[nf][0], Bf[nf][1]);
                ldsm2(stb + (BL_OFF + idxB[nf][kpb]) * 4, Mf[nf][0], Mf[nf][1]);
            }
            unsigned Aa[4][4], Ll[4][4];
            #pragma unroll
            for (int mf = 0; mf < 4; mf++) {
                ldsm4(stb + (AH_OFF + idxA[mf][kpb]) * 4,
                      Aa[mf][0], Aa[mf][1], Aa[mf][2], Aa[mf][3]);
                ldsm4(stb + (AL_OFF + idxA[mf][kpb]) * 4,
                      Ll[mf][0], Ll[mf][1], Ll[mf][2], Ll[mf][3]);
            }
            #pragma unroll
            for (int mf = 0; mf < 4; mf++)
                #pragma unroll
                for (int nf = 0; nf < 8; nf++)
                    mma16(acc[mf][nf], Aa[mf], Mf[nf]);
            #pragma unroll
            for (int mf = 0; mf < 4; mf++)
                #pragma unroll
                for (int nf = 0; nf < 8; nf++)
                    mma16(acc[mf][nf], Ll[mf], Bf[nf]);
            #pragma unroll
            for (int mf = 0; mf < 4; mf++)
                #pragma unroll
                for (int nf = 0; nf < 8; nf++)
                    mma16(acc[mf][nf], Aa[mf], Bf[nf]);
        }
    }

    // ---- epilogue ----
    #pragma unroll
    for (int mf = 0; mf < 4; mf++) {
        const int r0 = by * 128 + wm + mf * 16 + g;
        #pragma unroll
        for (int nf = 0; nf < 8; nf++) {
            const int col = bx * 128 + wn + nf * 8 + tc * 2;
            float c0 = acc[mf][nf][0], c1 = acc[mf][nf][1];
            float c2 = acc[mf][nf][2], c3 = acc[mf][nf][3];
            if (EPI >= 1) {
                const float b0v = bias[col], b1v = bias[col + 1];
                c0 += b0v; c1 += b1v; c2 += b0v; c3 += b1v;
            }
            if (EPI == 2) {
                c0 = 0.5f * c0 * (1.0f + erff(c0 * 0.7071067811865475f));
                c1 = 0.5f * c1 * (1.0f + erff(c1 * 0.7071067811865475f));
                c2 = 0.5f * c2 * (1.0f + erff(c2 * 0.7071067811865475f));
                c3 = 0.5f * c3 * (1.0f + erff(c3 * 0.7071067811865475f));
            }
            if (OUT == 0) {
                *(float2*)&C[coff + (size_t)r0 * ldc + col]       = make_float2(c0, c1);
                *(float2*)&C[coff + (size_t)(r0 + 8) * ldc + col] = make_float2(c2, c3);
            } else {
                __nv_bfloat162 H, L;
                split2(c0, c1, H, L);
                *(__nv_bfloat162*)&Ch[coff + (size_t)r0 * ldc + col] = H;
                *(__nv_bfloat162*)&Cl[coff + (size_t)r0 * ldc + col] = L;
                split2(c2, c3, H, L);
                *(__nv_bfloat162*)&Ch[coff + (size_t)(r0 + 8) * ldc + col] = H;
                *(__nv_bfloat162*)&Cl[coff + (size_t)(r0 + 8) * ldc + col] = L;
            }
        }
    }
}

// ---------------------------------------------------------------------------
// Split-K reduction: out = bias + sum of 4 partial planes. float4 vectorized.
// ---------------------------------------------------------------------------
__global__ void reduce_k(const float* __restrict__ P, const float* __restrict__ bias,
                         float* __restrict__ out, int n, int total4)
{
    const int i = blockIdx.x * 256 + threadIdx.x;
    if (i >= total4) return;
    float4 a = ((const float4*)P)[i];
    #pragma unroll
    for (int s = 1; s < 4; s++) {
        float4 b = ((const float4*)P)[i + (size_t)s * total4];
        a.x += b.x; a.y += b.y; a.z += b.z; a.w += b.w;
    }
    const int c = (i * 4) & (n - 1);
    a.x += bias[c]; a.y += bias[c + 1]; a.z += bias[c + 2]; a.w += bias[c + 3];
    ((float4*)out)[i] = a;
}

// ---------------------------------------------------------------------------
// Weight transpose + split: src fp32 [K][N] -> dst bf16 hi/lo [N][K].
// ---------------------------------------------------------------------------
__global__ void wconv(const float* __restrict__ src,
                      __nv_bfloat16* __restrict__ dh, __nv_bfloat16* __restrict__ dl,
                      int K, int N)
{
    __shared__ float t[32][33];
    const int k0 = blockIdx.x * 32, n0 = blockIdx.y * 32;
    const int tx = threadIdx.x, ty = threadIdx.y;
    #pragma unroll
    for (int r = 0; r < 4; r++)
        t[ty + r * 8][tx] = src[(size_t)(k0 + ty + r * 8) * N + n0 + tx];
    __syncthreads();
    #pragma unroll
    for (int r = 0; r < 4; r++) {
        const float v = t[tx][ty + r * 8];
        const size_t o = (size_t)(n0 + ty + r * 8) * K + k0 + tx;
        splitw(v, dh + o, dl + o);
    }
}

// Fused Wq/Wk/Wv transpose+split into one [QKVN][KD] buffer. grid z picks src.
__global__ void wconv3(const float* __restrict__ s0, const float* __restrict__ s1,
                       const float* __restrict__ s2,
                       __nv_bfloat16* __restrict__ dh, __nv_bfloat16* __restrict__ dl)
{
    __shared__ float t[32][33];
    const float* src = (blockIdx.z == 0) ? s0 : (blockIdx.z == 1 ? s1 : s2);
    const int k0 = blockIdx.x * 32, n0 = blockIdx.y * 32;
    const int tx = threadIdx.x, ty = threadIdx.y;
    #pragma unroll
    for (int r = 0; r < 4; r++)
        t[ty + r * 8][tx] = src[(size_t)(k0 + ty + r * 8) * HK + n0 + tx];
    __syncthreads();
    const size_t rowoff = (size_t)blockIdx.z * HK;
    #pragma unroll
    for (int r = 0; r < 4; r++) {
        const float v = t[tx][ty + r * 8];
        const size_t o = (rowoff + n0 + ty + r * 8) * KD + k0 + tx;
        splitw(v, dh + o, dl + o);
    }
}

// ---------------------------------------------------------------------------
// V transpose+split per head from the fused QKV split buffer.
// ---------------------------------------------------------------------------
__global__ void vconv2(const __nv_bfloat16* __restrict__ vh,
                       const __nv_bfloat16* __restrict__ vl,
                       __nv_bfloat16* __restrict__ dh, __nv_bfloat16* __restrict__ dl)
{
    __shared__ float t[32][33];
    const int z = blockIdx.z, b = z >> 3, h = z & 7;
    const int t0 = blockIdx.x * 32, d0 = blockIdx.y * 32;
    const int tx = threadIdx.x, ty = threadIdx.y;
    #pragma unroll
    for (int r = 0; r < 4; r++) {
        const size_t si = (size_t)(b * SEQ + t0 + ty + r * 8) * QKVN
                        + 2 * HK + h * KD + d0 + tx;
        t[ty + r * 8][tx] = __bfloat162float(vh[si]) + __bfloat162float(vl[si]);
    }
    __syncthreads();
    #pragma unroll
    for (int r = 0; r < 4; r++) {
        const float val = t[tx][ty + r * 8];
        const size_t o = ((size_t)z * KD + d0 + ty + r * 8) * SEQ + t0 + tx;
        splitw(val, dh + o, dl + o);
    }
}

// ---------------------------------------------------------------------------
// Embedding + positional encoding (+ split).
// ---------------------------------------------------------------------------
__global__ void embed_k(const int* __restrict__ x, const float* __restrict__ W,
                        float* __restrict__ h,
                        __nv_bfloat16* __restrict__ hh, __nv_bfloat16* __restrict__ hl)
{
    const int token = blockIdx.x;
    const int t  = token & (SEQ - 1);
    const int id = x[token];
    const int tid = threadIdx.x;
    #pragma unroll
    for (int u = 0; u < 2; u++) {
        const int c = tid + u * 256;
        const int j = c >> 1;
        const float ang = (float)t * expf(-(float)j * 0.07195578415606394f);
        const float p = (c & 1) ? cosf(ang) : sinf(ang);
        const float val = W[(size_t)id * KD + c] + p;
        const size_t o = (size_t)token * KD + c;
        h[o] = val;
        splitw(val, hh + o, hl + o);
    }
}

// ---------------------------------------------------------------------------
// Causal softmax (scale folded), writes split bf16. grid(SEQ, 32), 256 thr.
// ---------------------------------------------------------------------------
__global__ void softmax_k(const float* __restrict__ att,
                          __nv_bfloat16* __restrict__ oh, __nv_bfloat16* __restrict__ ol)
{
    const int q  = blockIdx.x;
    const int bh = blockIdx.y;
    const size_t base = ((size_t)bh * SEQ + q) * SEQ;
    const int tid = threadIdx.x;
    const float scale = 0.04419417382415922f;  // 1/sqrt(512)
    __shared__ float red[256];

    const float s0 = (tid       <= q) ? att[base + tid]       * scale : -3.4e38f;
    const float s1 = (tid + 256 <= q) ? att[base + tid + 256] * scale : -3.4e38f;
    red[tid] = fmaxf(s0, s1);
    __syncthreads();
    for (int o = 128; o; o >>= 1) {
        if (tid < o) red[tid] = fmaxf(red[tid], red[tid + o]);
        __syncthreads();
    }
    const float m = red[0];
    __syncthreads();
    const float v0 = (tid       <= q) ? expf(s0 - m) : 0.f;
    const float v1 = (tid + 256 <= q) ? expf(s1 - m) : 0.f;
    red[tid] = v0 + v1;
    __syncthreads();
    for (int o = 128; o; o >>= 1) {
        if (tid < o) red[tid] += red[tid + o];
        __syncthreads();
    }
    const float inv = 1.0f / red[0];
    splitw(v0 * inv, oh + base + tid,       ol + base + tid);
    splitw(v1 * inv, oh + base + tid + 256, ol + base + tid + 256);
}

// ---------------------------------------------------------------------------
// (optional residual) + LayerNorm (+ split).
// ---------------------------------------------------------------------------
__global__ void ln_k(const float* __restrict__ src, float* __restrict__ h,
                     __nv_bfloat16* __restrict__ hh, __nv_bfloat16* __restrict__ hl,
                     const float* __restrict__ w, const float* __restrict__ b,
                     int residual)
{
    const int token = blockIdx.x;
    const size_t base = (size_t)token * KD;
    const int tid = threadIdx.x;
    float x0 = src[base + tid];
    float x1 = src[base + tid + 256];
    if (residual) { x0 += h[base + tid]; x1 += h[base + tid + 256]; }
    __shared__ float s1[256], s2[256];
    s1[tid] = x0 + x1;
    s2[tid] = x0 * x0 + x1 * x1;
    __syncthreads();
    for (int o = 128; o; o >>= 1) {
        if (tid < o) { s1[tid] += s1[tid + o]; s2[tid] += s2[tid + o]; }
        __syncthreads();
    }
    const float mean = s1[0] * (1.f / KD);
    const float var  = s2[0] * (1.f / KD) - mean * mean;
    const float r = rsqrtf(var + 1e-5f);
    const float y0 = (x0 - mean) * r * w[tid]       + b[tid];
    const float y1 = (x1 - mean) * r * w[tid + 256] + b[tid + 256];
    h[base + tid]       = y0;
    h[base + tid + 256] = y1;
    splitw(y0, hh + base + tid,       hl + base + tid);
    splitw(y1, hh + base + tid + 256, hl + base + tid + 256);
}

// ---------------------------------------------------------------------------
// Host-side launcher
// ---------------------------------------------------------------------------
struct GemmArgs {
    const __nv_bfloat16 *Ah, *Al, *Bh, *Bl;
    const float* bias;
    float* C;
    __nv_bfloat16 *Ch, *Cl;
    int M, N, K, lda, ldb, ldc;
    long aO, aI, bO, bI, cO, cI;
    int zdiv, batches, causal;
};

template<int EPI, int OUT>
static void launch_gemm(const GemmArgs& a)
{
    static bool attr_set = false;
    if (!attr_set) {
        cudaFuncSetAttribute(gemm_ps<EPI, OUT>,
                             cudaFuncAttributeMaxDynamicSharedMemorySize, GEMM_SMEM);
        attr_set = true;
    }
    dim3 grid(a.N / 128, a.M / 128, a.batches), block(128);
    gemm_ps<EPI, OUT><<<grid, block, GEMM_SMEM>>>(
        a.Ah, a.Al, a.Bh, a.Bl, a.bias, a.C, a.Ch, a.Cl,
        a.M, a.N, a.K, a.lda, a.ldb, a.ldc,
        a.aO, a.aI, a.bO, a.bI, a.cO, a.cI, a.zdiv, a.causal);
}

extern "C" void kernel_launch(void* const* d_in, const int* in_sizes, int n_in,
                              void* d_out, int out_size)
{
    const int*   x        = (const int*)  d_in[0];
    const float* embed_W  = (const float*)d_in[1];
    const float* Wq       = (const float*)d_in[2];
    const float* Wk       = (const float*)d_in[3];
    const float* Wv       = (const float*)d_in[4];
    const float* Wu       = (const float*)d_in[5];
    const float* bu       = (const float*)d_in[6];
    const float* W1       = (const float*)d_in[7];
    const float* b1       = (const float*)d_in[8];
    const float* W2       = (const float*)d_in[9];
    const float* b2       = (const float*)d_in[10];
    const float* ln1_w    = (const float*)d_in[11];
    const float* ln1_b    = (const float*)d_in[12];
    const float* ln2_w    = (const float*)d_in[13];
    const float* ln2_b    = (const float*)d_in[14];
    const float* lnf_w    = (const float*)d_in[15];
    const float* lnf_b    = (const float*)d_in[16];
    const float* unembedW = (const float*)d_in[17];
    const float* unembedB = (const float*)d_in[18];
    float* out = (float*)d_out;

    float *h, *att, *tmp;
    __nv_bfloat16 *hsh, *hsl, *wth, *wtl, *qvh, *qvl,
                  *vth, *vtl, *ash, *asl, *ysh, *ysl, *fsh, *fsl;
    cudaGetSymbolAddress((void**)&h,   g_h);
    cudaGetSymbolAddress((void**)&att, g_att);
    cudaGetSymbolAddress((void**)&tmp, g_tmp);
    cudaGetSymbolAddress((void**)&hsh, g_hs_h); cudaGetSymbolAddress((void**)&hsl, g_hs_l);
    cudaGetSymbolAddress((void**)&wth, g_wt_h); cudaGetSymbolAddress((void**)&wtl, g_wt_l);
    cudaGetSymbolAddress((void**)&qvh, g_qkv_h); cudaGetSymbolAddress((void**)&qvl, g_qkv_l);
    cudaGetSymbolAddress((void**)&vth, g_vt_h); cudaGetSymbolAddress((void**)&vtl, g_vt_l);
    cudaGetSymbolAddress((void**)&ash, g_as_h); cudaGetSymbolAddress((void**)&asl, g_as_l);
    cudaGetSymbolAddress((void**)&ysh, g_ys_h); cudaGetSymbolAddress((void**)&ysl, g_ys_l);
    cudaGetSymbolAddress((void**)&fsh, g_fs_h); cudaGetSymbolAddress((void**)&fsl, g_fs_l);

    embed_k<<<MTOK, 256>>>(x, embed_W, h, hsh, hsl);

    const long atI = (long)SEQ * SEQ;          // 262144
    const long atO = (long)HEADS * atI;

    for (int i = 0; i < NBLK; i++) {
        const float* Wq_i = Wq + (size_t)i * KD * HK;
        const float* Wk_i = Wk + (size_t)i * KD * HK;
        const float* Wv_i = Wv + (size_t)i * KD * HK;
        const float* Wu_i = Wu + (size_t)i * HK * KD;
        const float* bu_i = bu + (size_t)i * KD;
        const float* W1_i = W1 + (size_t)i * KD * FF;
        const float* b1_i = b1 + (size_t)i * FF;
        const float* W2_i = W2 + (size_t)i * FF * KD;
        const float* b2_i = b2 + (size_t)i * KD;

        // fused QKV
        wconv3<<<dim3(KD/32, HK/32, 3), dim3(32,8)>>>(Wq_i, Wk_i, Wv_i, wth, wtl);
        { GemmArgs a = {hsh, hsl, wth, wtl, nullptr, nullptr, qvh, qvl,
                        MTOK, QKVN, KD, KD, KD, QKVN, 0,0,0,0,0,0, 1, 1, 0};
          launch_gemm<0,1>(a); }

        // scores = Q @ K^T; skip upper-triangle tiles
        { GemmArgs a = {qvh, qvl, qvh + HK, qvl + HK, nullptr, att, nullptr, nullptr,
                        SEQ, SEQ, KD, QKVN, QKVN, SEQ,
                        (long)SEQ*QKVN, (long)KD, (long)SEQ*QKVN, (long)KD,
                        atO, atI, HEADS, NBH, 1};
          launch_gemm<0,0>(a); }

        softmax_k<<<dim3(SEQ, NBH), 256>>>(att, ash, asl);
        vconv2<<<dim3(16,16,NBH), dim3(32,8)>>>(qvh, qvl, vth, vtl);

        // y = att @ V; truncate K per tile row
        { GemmArgs a = {ash, asl, vth, vtl, nullptr, nullptr, ysh, ysl,
                        SEQ, KD, SEQ, SEQ, SEQ, HK,
                        atO, atI, atO, atI,
                        (long)SEQ*HK, (long)KD, HEADS, NBH, 2};
          launch_gemm<0,1>(a); }

        // proj: split-K=4 -> partials in att -> reduce+bias
        wconv<<<dim3(HK/32, KD/32), dim3(32,8)>>>(Wu_i, wth, wtl, HK, KD);
        { GemmArgs a = {ysh, ysl, wth, wtl, nullptr, att, nullptr, nullptr,
                        MTOK, KD, 1024, HK, HK, KD,
                        1024, 0, 1024, 0, (long)MTOK*KD, 0, 1, 4, 0};
          launch_gemm<0,0>(a); }
        reduce_k<<<(MTOK*KD/4 + 255)/256, 256>>>(att, bu_i, tmp, KD, MTOK*KD/4);

        ln_k<<<MTOK, 256>>>(tmp, h, hsh, hsl,
                            ln1_w + (size_t)i * KD, ln1_b + (size_t)i * KD, 1);

        // ff = gelu(h @ W1 + b1)
        wconv<<<dim3(KD/32, FF/32), dim3(32,8)>>>(W1_i, wth, wtl, KD, FF);
        { GemmArgs a = {hsh, hsl, wth, wtl, b1_i, nullptr, fsh, fsl,
                        MTOK, FF, KD, KD, KD, FF, 0,0,0,0,0,0, 1, 1, 0};
          launch_gemm<2,1>(a); }

        // tmp = ff @ W2 + b2: split-K=4 -> partials -> reduce
        wconv<<<dim3(FF/32, KD/32), dim3(32,8)>>>(W2_i, wth, wtl, FF, KD);
        { GemmArgs a = {fsh, fsl, wth, wtl, nullptr, att, nullptr, nullptr,
                        MTOK, KD, 512, FF, FF, KD,
                        512, 0, 512, 0, (long)MTOK*KD, 0, 1, 4, 0};
          launch_gemm<0,0>(a); }
        reduce_k<<<(MTOK*KD/4 + 255)/256, 256>>>(att, b2_i, tmp, KD, MTOK*KD/4);

        ln_k<<<MTOK, 256>>>(tmp, h, hsh, hsl,
                            ln2_w + (size_t)i * KD, ln2_b + (size_t)i * KD, 1);
    }

    ln_k<<<MTOK, 256>>>(h, h, hsh, hsl, lnf_w, lnf_b, 0);

    // unembed
    wconv<<<dim3(KD/32, VOCAB/32), dim3(32,8)>>>(unembedW, wth, wtl, KD, VOCAB);
    { GemmArgs a = {hsh, hsl, wth, wtl, unembedB, out, nullptr, nullptr,
                    MTOK, VOCAB, KD, KD, KD, VOCAB, 0,0,0,0,0,0, 1, 1, 0};
      launch_gemm<1,0>(a); }
}

// round 13
// speedup vs baseline: 2.1377x; 2.1377x over previous
#include <cuda_runtime.h>
#include <cuda_bf16.h>
#include <cuda_fp16.h>
#include <math.h>

// ---------------------------------------------------------------------------
// GPT forward. Mixed-precision tensor-core GEMMs with cp.async pipeline.
// B=4, T=512, K=512, H=8, NB=4, VOCAB=32000. M = B*T = 2048 tokens.
//
// R13: fp16 single-pass (1 MMA/k16) for QKV, scores, attV, unembed;
// bf16x3 split (3 MMA/k16) for proj, W1, W2 (residual-stream writers).
// R9 GEMM core (256 thr, 64x32 warp tiles, 3-stage cp.async, 2 CTA/SM),
// split-K skinny GEMMs, fused QKV, causal skip/truncate.
// ---------------------------------------------------------------------------

#define BATCH 4
#define SEQ   512
#define KD    512
#define HEADS 8
#define NBLK  4
#define VOCAB 32000
#define MTOK  (BATCH*SEQ)        // 2048
#define HK    (HEADS*KD)         // 4096
#define QKVN  (3*HK)             // 12288
#define FF    (4*KD)             // 2048
#define NBH   (BATCH*HEADS)      // 32

// fp32 scratch
__device__ float g_h  [MTOK*KD];
__device__ float g_att[NBH*SEQ*SEQ];      // scores; reused as split-K partials
__device__ float g_tmp[MTOK*KD];
// 16-bit scratch (bf16 split or fp16, per use)
__device__ __align__(256) __nv_bfloat16 g_hs_h[MTOK*KD],  g_hs_l[MTOK*KD];
__device__ __align__(256) __half         g_hf  [MTOK*KD];          // fp16 hidden
__device__ __align__(256) __nv_bfloat16 g_wt_h[(size_t)VOCAB*KD], g_wt_l[(size_t)VOCAB*KD];
__device__ __align__(256) __half         g_qkv [(size_t)MTOK*QKVN]; // fp16 QKV
__device__ __align__(256) __half         g_vt  [MTOK*HK];           // fp16 V^T
__device__ __align__(256) __half         g_as  [NBH*SEQ*SEQ];       // fp16 att
__device__ __align__(256) __nv_bfloat16 g_ys_h[MTOK*HK],  g_ys_l[MTOK*HK];
__device__ __align__(256) __nv_bfloat16 g_fs_h[MTOK*FF],  g_fs_l[MTOK*FF];

// ---------------------------------------------------------------------------
// helpers
// ---------------------------------------------------------------------------
__device__ __forceinline__ unsigned smem_u32(const void* p) {
    unsigned r;
    asm("{ .reg .u64 t; cvta.to.shared.u64 t, %1; cvt.u32.u64 %0, t; }"
        : "=r"(r) : "l"(p));
    return r;
}
__device__ __forceinline__ void cp16(unsigned dst, const void* src) {
    asm volatile("cp.async.cg.shared.global [%0], [%1], 16;" :: "r"(dst), "l"(src));
}
#define CP_COMMIT() asm volatile("cp.async.commit_group;" ::: "memory")
#define CP_WAIT1()  asm volatile("cp.async.wait_group 1;" ::: "memory")

__device__ __forceinline__ void ldsm4(unsigned addr, unsigned& r0, unsigned& r1,
                                      unsigned& r2, unsigned& r3) {
    asm volatile("ldmatrix.sync.aligned.m8n8.x4.shared.b16 {%0,%1,%2,%3}, [%4];"
                 : "=r"(r0), "=r"(r1), "=r"(r2), "=r"(r3) : "r"(addr));
}
__device__ __forceinline__ void ldsm2(unsigned addr, unsigned& r0, unsigned& r1) {
    asm volatile("ldmatrix.sync.aligned.m8n8.x2.shared.b16 {%0,%1}, [%2];"
                 : "=r"(r0), "=r"(r1) : "r"(addr));
}
__device__ __forceinline__ void mma_bf16(float* c, const unsigned* a, const unsigned* b) {
    asm volatile(
        "mma.sync.aligned.m16n8k16.row.col.f32.bf16.bf16.f32 "
        "{%0,%1,%2,%3},{%4,%5,%6,%7},{%8,%9},{%0,%1,%2,%3};"
        : "+f"(c[0]), "+f"(c[1]), "+f"(c[2]), "+f"(c[3])
        : "r"(a[0]), "r"(a[1]), "r"(a[2]), "r"(a[3]), "r"(b[0]), "r"(b[1]));
}
__device__ __forceinline__ void mma_f16(float* c, const unsigned* a, const unsigned* b) {
    asm volatile(
        "mma.sync.aligned.m16n8k16.row.col.f32.f16.f16.f32 "
        "{%0,%1,%2,%3},{%4,%5,%6,%7},{%8,%9},{%0,%1,%2,%3};"
        : "+f"(c[0]), "+f"(c[1]), "+f"(c[2]), "+f"(c[3])
        : "r"(a[0]), "r"(a[1]), "r"(a[2]), "r"(a[3]), "r"(b[0]), "r"(b[1]));
}
__device__ __forceinline__ void splitw(float v, __nv_bfloat16* ph, __nv_bfloat16* pl) {
    __nv_bfloat16 hi = __float2bfloat16(v);
    *ph = hi;
    *pl = __float2bfloat16(v - __bfloat162float(hi));
}
__device__ __forceinline__ void split2(float a, float b,
                                       __nv_bfloat162& H, __nv_bfloat162& L) {
    __nv_bfloat16 ha = __float2bfloat16(a), hb = __float2bfloat16(b);
    H = __halves2bfloat162(ha, hb);
    L = __halves2bfloat162(__float2bfloat16(a - __bfloat162float(ha)),
                           __float2bfloat16(b - __bfloat162float(hb)));
}

// SMEM stage layout (uint32 units): [AH 2048 | AL 2048 | BH 2048 | BL 2048]
// Tile row = 16 uint32 (32 x 16-bit along k), swizzle col' = c ^ ((row&6)<<1).
#define ST_U32 8192
#define AH_OFF 0
#define AL_OFF 2048
#define BH_OFF 4096
#define BL_OFF 6144
#define NSTAGE 3
#define GEMM_SMEM (NSTAGE*ST_U32*4)   // 98304 bytes

// ---------------------------------------------------------------------------
// Pipelined GEMM. DT: 0 = bf16x3 split (A/B hi+lo), 1 = fp16 single (hi only).
// EPI: 0 none, 1 +bias, 2 gelu(x+bias).
// OUT: 0 fp32 C; 1 split bf16 Ch/Cl; 2 fp16 Ch.
// causal: 0 none, 1 tile-skip (bx>by), 2 K-trunc to (by+1)*128.
// Batched / split-K via blockIdx.z with strides. M%128==0, N%128==0, K%32==0.
// ---------------------------------------------------------------------------
template<int EPI, int OUT, int DT>
__global__ __launch_bounds__(256, 2)
void gemm_ps(const __nv_bfloat16* __restrict__ Ah, const __nv_bfloat16* __restrict__ Al,
             const __nv_bfloat16* __restrict__ Bh, const __nv_bfloat16* __restrict__ Bl,
             const float* __restrict__ bias,
             float* __restrict__ C,
             __nv_bfloat16* __restrict__ Ch, __nv_bfloat16* __restrict__ Cl,
             int M, int N, int K, int lda, int ldb, int ldc,
             long aO, long aI, long bO, long bI, long cO, long cI, int zdiv,
             int causal)
{
    extern __shared__ unsigned sm[];
    const unsigned base32 = smem_u32(sm);

    const int bx = blockIdx.x, by = blockIdx.y;
    if (causal == 1 && bx > by) return;
    if (causal == 2) K = min(K, (by + 1) * 128);

    const int z  = blockIdx.z;
    const int zb = z / zdiv, zh = z - zb * zdiv;
    const size_t aoff = (size_t)zb * aO + (size_t)zh * aI;
    const size_t boff = (size_t)zb * bO + (size_t)zh * bI;
    const size_t coff = (size_t)zb * cO + (size_t)zh * cI;
    Ah += aoff; Bh += boff;
    if (DT == 0) { Al += aoff; Bl += boff; }

    const int tid  = threadIdx.x;
    const int lane = tid & 31;
    const int warp = tid >> 5;
    const int g    = lane >> 2;
    const int tc   = lane & 3;
    const int wm   = (warp >> 2) * 64;
    const int wn   = (warp & 3) * 32;

    const int crow = tid >> 1;
    const int cj   = (tid & 1) * 2;
    const __nv_bfloat16* pAh = Ah + (size_t)(by * 128 + crow) * lda + cj * 8;
    const __nv_bfloat16* pAl = (DT == 0) ? Al + (size_t)(by * 128 + crow) * lda + cj * 8 : nullptr;
    const __nv_bfloat16* pBh = Bh + (size_t)(bx * 128 + crow) * ldb + cj * 8;
    const __nv_bfloat16* pBl = (DT == 0) ? Bl + (size_t)(bx * 128 + crow) * ldb + cj * 8 : nullptr;
    const int csw = (crow & 6) << 1;
    const int cs0 = crow * 16 + ((4 * cj)     ^ csw);
    const int cs1 = crow * 16 + ((4 * cj + 4) ^ csw);

    int idxA[4][2], idxB[4][2];
    {
        const int rowA = wm + (lane & 15);
        const int cgA0 = (lane >> 4) << 2;
        const int rowB = wn + (lane & 7);
        const int cgB0 = ((lane >> 3) & 1) << 2;
        #pragma unroll
        for (int mf = 0; mf < 4; mf++) {
            const int r = rowA + mf * 16;
            idxA[mf][0] = r * 16 + ((cgA0)     ^ ((r & 6) << 1));
            idxA[mf][1] = r * 16 + ((cgA0 + 8) ^ ((r & 6) << 1));
        }
        #pragma unroll
        for (int nf = 0; nf < 4; nf++) {
            const int r = rowB + nf * 8;
            idxB[nf][0] = r * 16 + ((cgB0)     ^ ((r & 6) << 1));
            idxB[nf][1] = r * 16 + ((cgB0 + 8) ^ ((r & 6) << 1));
        }
    }

    float acc[4][4][4];
    #pragma unroll
    for (int i = 0; i < 4; i++)
        #pragma unroll
        for (int j = 0; j < 4; j++)
            #pragma unroll
            for (int r = 0; r < 4; r++) acc[i][j][r] = 0.f;

    auto ISSUE = [&](int buf, int k0) {
        const unsigned sb = base32 + buf * (ST_U32 * 4);
        cp16(sb + (AH_OFF + cs0) * 4, pAh + k0);
        cp16(sb + (AH_OFF + cs1) * 4, pAh + k0 + 8);
        cp16(sb + (BH_OFF + cs0) * 4, pBh + k0);
        cp16(sb + (BH_OFF + cs1) * 4, pBh + k0 + 8);
        if (DT == 0) {
            cp16(sb + (AL_OFF + cs0) * 4, pAl + k0);
            cp16(sb + (AL_OFF + cs1) * 4, pAl + k0 + 8);
            cp16(sb + (BL_OFF + cs0) * 4, pBl + k0);
            cp16(sb + (BL_OFF + cs1) * 4, pBl + k0 + 8);
        }
    };

    const int nc = K >> 5;

    ISSUE(0, 0);  CP_COMMIT();
    if (nc > 1) ISSUE(1, 32);
    CP_COMMIT();

    for (int i = 0; i < nc; i++) {
        CP_WAIT1();
        __syncthreads();

        if (i + 2 < nc) ISSUE((i + 2) % NSTAGE, (i + 2) * 32);
        CP_COMMIT();

        const unsigned stb = base32 + (i % NSTAGE) * (ST_U32 * 4);
        #pragma unroll
        for (int kpb = 0; kpb < 2; kpb++) {
            if (DT == 0) {
                unsigned Bf[4][2], Mf[4][2];
                #pragma unroll
                for (int nf = 0; nf < 4; nf++) {
                    ldsm2(stb + (BH_OFF + idxB[nf][kpb]) * 4, Bf[nf][0], Bf[nf][1]);
                    ldsm2(stb + (BL_OFF + idxB[nf][kpb]) * 4, Mf[nf][0], Mf[nf][1]);
                }
                #pragma unroll
                for (int mf = 0; mf < 4; mf++) {
                    unsigned Aa[4], Ll[4];
                    ldsm4(stb + (AH_OFF + idxA[mf][kpb]) * 4, Aa[0], Aa[1], Aa[2], Aa[3]);
                    ldsm4(stb + (AL_OFF + idxA[mf][kpb]) * 4, Ll[0], Ll[1], Ll[2], Ll[3]);
                    #pragma unroll
                    for (int nf = 0; nf < 4; nf++) {
                        mma_bf16(acc[mf][nf], Aa, Mf[nf]);
                        mma_bf16(acc[mf][nf], Ll, Bf[nf]);
                        mma_bf16(acc[mf][nf], Aa, Bf[nf]);
                    }
                }
            } else {
                unsigned Bf[4][2];
                #pragma unroll
                for (int nf = 0; nf < 4; nf++)
                    ldsm2(stb + (BH_OFF + idxB[nf][kpb]) * 4, Bf[nf][0], Bf[nf][1]);
                #pragma unroll
                for (int mf = 0; mf < 4; mf++) {
                    unsigned Aa[4];
                    ldsm4(stb + (AH_OFF + idxA[mf][kpb]) * 4, Aa[0], Aa[1], Aa[2], Aa[3]);
                    #pragma unroll
                    for (int nf = 0; nf < 4; nf++)
                        mma_f16(acc[mf][nf], Aa, Bf[nf]);
                }
            }
        }
    }

    // ---- epilogue ----
    #pragma unroll
    for (int mf = 0; mf < 4; mf++) {
        const int r0 = by * 128 + wm + mf * 16 + g;
        #pragma unroll
        for (int nf = 0; nf < 4; nf++) {
            const int col = bx * 128 + wn + nf * 8 + tc * 2;
            float c0 = acc[mf][nf][0], c1 = acc[mf][nf][1];
            float c2 = acc[mf][nf][2], c3 = acc[mf][nf][3];
            if (EPI >= 1) {
                const float b0v = bias[col], b1v = bias[col + 1];
                c0 += b0v; c1 += b1v; c2 += b0v; c3 += b1v;
            }
            if (EPI == 2) {
                c0 = 0.5f * c0 * (1.0f + erff(c0 * 0.7071067811865475f));
                c1 = 0.5f * c1 * (1.0f + erff(c1 * 0.7071067811865475f));
                c2 = 0.5f * c2 * (1.0f + erff(c2 * 0.7071067811865475f));
                c3 = 0.5f * c3 * (1.0f + erff(c3 * 0.7071067811865475f));
            }
            if (OUT == 0) {
                *(float2*)&C[coff + (size_t)r0 * ldc + col]       = make_float2(c0, c1);
                *(float2*)&C[coff + (size_t)(r0 + 8) * ldc + col] = make_float2(c2, c3);
            } else if (OUT == 1) {
                __nv_bfloat162 H, L;
                split2(c0, c1, H, L);
                *(__nv_bfloat162*)&Ch[coff + (size_t)r0 * ldc + col] = H;
                *(__nv_bfloat162*)&Cl[coff + (size_t)r0 * ldc + col] = L;
                split2(c2, c3, H, L);
                *(__nv_bfloat162*)&Ch[coff + (size_t)(r0 + 8) * ldc + col] = H;
                *(__nv_bfloat162*)&Cl[coff + (size_t)(r0 + 8) * ldc + col] = L;
            } else {
                __half2* dst0 = (__half2*)&Ch[coff + (size_t)r0 * ldc + col];
                __half2* dst1 = (__half2*)&Ch[coff + (size_t)(r0 + 8) * ldc + col];
                *dst0 = __floats2half2_rn(c0, c1);
                *dst1 = __floats2half2_rn(c2, c3);
            }
        }
    }
}

// ---------------------------------------------------------------------------
// Split-K reduction: out = bias + sum of 4 partial planes.
// ---------------------------------------------------------------------------
__global__ void reduce_k(const float* __restrict__ P, const float* __restrict__ bias,
                         float* __restrict__ out, int n, int total4)
{
    const int i = blockIdx.x * 256 + threadIdx.x;
    if (i >= total4) return;
    float4 a = ((const float4*)P)[i];
    #pragma unroll
    for (int s = 1; s < 4; s++) {
        float4 b = ((const float4*)P)[i + (size_t)s * total4];
        a.x += b.x; a.y += b.y; a.z += b.z; a.w += b.w;
    }
    const int c = (i * 4) & (n - 1);
    a.x += bias[c]; a.y += bias[c + 1]; a.z += bias[c + 2]; a.w += bias[c + 3];
    ((float4*)out)[i] = a;
}

// ---------------------------------------------------------------------------
// Weight transpose + split bf16: src fp32 [K][N] -> dst bf16 hi/lo [N][K].
// ---------------------------------------------------------------------------
__global__ void wconv(const float* __restrict__ src,
                      __nv_bfloat16* __restrict__ dh, __nv_bfloat16* __restrict__ dl,
                      int K, int N)
{
    __shared__ float t[32][33];
    const int k0 = blockIdx.x * 32, n0 = blockIdx.y * 32;
    const int tx = threadIdx.x, ty = threadIdx.y;
    #pragma unroll
    for (int r = 0; r < 4; r++)
        t[ty + r * 8][tx] = src[(size_t)(k0 + ty + r * 8) * N + n0 + tx];
    __syncthreads();
    #pragma unroll
    for (int r = 0; r < 4; r++) {
        const float v = t[tx][ty + r * 8];
        const size_t o = (size_t)(n0 + ty + r * 8) * K + k0 + tx;
        splitw(v, dh + o, dl + o);
    }
}

// Weight transpose, fp16 single: src fp32 [K][N] -> dst fp16 [N][K].
__global__ void wconvh(const float* __restrict__ src, __half* __restrict__ dh,
                       int K, int N)
{
    __shared__ float t[32][33];
    const int k0 = blockIdx.x * 32, n0 = blockIdx.y * 32;
    const int tx = threadIdx.x, ty = threadIdx.y;
    #pragma unroll
    for (int r = 0; r < 4; r++)
        t[ty + r * 8][tx] = src[(size_t)(k0 + ty + r * 8) * N + n0 + tx];
    __syncthreads();
    #pragma unroll
    for (int r = 0; r < 4; r++)
        dh[(size_t)(n0 + ty + r * 8) * K + k0 + tx] = __float2half(t[tx][ty + r * 8]);
}

// Fused Wq/Wk/Wv transpose -> fp16 [QKVN][KD]. grid z picks src.
__global__ void wconv3h(const float* __restrict__ s0, const float* __restrict__ s1,
                        const float* __restrict__ s2, __half* __restrict__ dh)
{
    __shared__ float t[32][33];
    const float* src = (blockIdx.z == 0) ? s0 : (blockIdx.z == 1 ? s1 : s2);
    const int k0 = blockIdx.x * 32, n0 = blockIdx.y * 32;
    const int tx = threadIdx.x, ty = threadIdx.y;
    #pragma unroll
    for (int r = 0; r < 4; r++)
        t[ty + r * 8][tx] = src[(size_t)(k0 + ty + r * 8) * HK + n0 + tx];
    __syncthreads();
    const size_t rowoff = (size_t)blockIdx.z * HK;
    #pragma unroll
    for (int r = 0; r < 4; r++)
        dh[(rowoff + n0 + ty + r * 8) * KD + k0 + tx] = __float2half(t[tx][ty + r * 8]);
}

// ---------------------------------------------------------------------------
// V transpose per head from fp16 QKV buffer -> fp16 [(b*8+h)*512+d][t].
// ---------------------------------------------------------------------------
__global__ void vconvh(const __half* __restrict__ qv, __half* __restrict__ dh)
{
    __shared__ __half t[32][33];
    const int z = blockIdx.z, b = z >> 3, h = z & 7;
    const int t0 = blockIdx.x * 32, d0 = blockIdx.y * 32;
    const int tx = threadIdx.x, ty = threadIdx.y;
    #pragma unroll
    for (int r = 0; r < 4; r++) {
        const size_t si = (size_t)(b * SEQ + t0 + ty + r * 8) * QKVN
                        + 2 * HK + h * KD + d0 + tx;
        t[ty + r * 8][tx] = qv[si];
    }
    __syncthreads();
    #pragma unroll
    for (int r = 0; r < 4; r++) {
        const size_t o = ((size_t)z * KD + d0 + ty + r * 8) * SEQ + t0 + tx;
        dh[o] = t[tx][ty + r * 8];
    }
}

// ---------------------------------------------------------------------------
// Embedding + positional encoding. Writes fp32 h, split bf16, and fp16.
// ---------------------------------------------------------------------------
__global__ void embed_k(const int* __restrict__ x, const float* __restrict__ W,
                        float* __restrict__ h,
                        __nv_bfloat16* __restrict__ hh, __nv_bfloat16* __restrict__ hl,
                        __half* __restrict__ hf)
{
    const int token = blockIdx.x;
    const int t  = token & (SEQ - 1);
    const int id = x[token];
    const int tid = threadIdx.x;
    #pragma unroll
    for (int u = 0; u < 2; u++) {
        const int c = tid + u * 256;
        const int j = c >> 1;
        const float ang = (float)t * expf(-(float)j * 0.07195578415606394f);
        const float p = (c & 1) ? cosf(ang) : sinf(ang);
        const float val = W[(size_t)id * KD + c] + p;
        const size_t o = (size_t)token * KD + c;
        h[o] = val;
        splitw(val, hh + o, hl + o);
        hf[o] = __float2half(val);
    }
}

// ---------------------------------------------------------------------------
// Causal softmax (scale folded), writes fp16 att. grid(SEQ, 32), 256 thr.
// ---------------------------------------------------------------------------
__global__ void softmax_k(const float* __restrict__ att, __half* __restrict__ oh)
{
    const int q  = blockIdx.x;
    const int bh = blockIdx.y;
    const size_t base = ((size_t)bh * SEQ + q) * SEQ;
    const int tid = threadIdx.x;
    const float scale = 0.04419417382415922f;  // 1/sqrt(512)
    __shared__ float red[256];

    const float s0 = (tid       <= q) ? att[base + tid]       * scale : -3.4e38f;
    const float s1 = (tid + 256 <= q) ? att[base + tid + 256] * scale : -3.4e38f;
    red[tid] = fmaxf(s0, s1);
    __syncthreads();
    for (int o = 128; o; o >>= 1) {
        if (tid < o) red[tid] = fmaxf(red[tid], red[tid + o]);
        __syncthreads();
    }
    const float m = red[0];
    __syncthreads();
    const float v0 = (tid       <= q) ? expf(s0 - m) : 0.f;
    const float v1 = (tid + 256 <= q) ? expf(s1 - m) : 0.f;
    red[tid] = v0 + v1;
    __syncthreads();
    for (int o = 128; o; o >>= 1) {
        if (tid < o) red[tid] += red[tid + o];
        __syncthreads();
    }
    const float inv = 1.0f / red[0];
    oh[base + tid]       = __float2half(v0 * inv);
    oh[base + tid + 256] = __float2half(v1 * inv);
}

// ---------------------------------------------------------------------------
// (optional residual) + LayerNorm. Writes fp32 h, split bf16, fp16.
// ---------------------------------------------------------------------------
__global__ void ln_k(const float* __restrict__ src, float* __restrict__ h,
                     __nv_bfloat16* __restrict__ hh, __nv_bfloat16* __restrict__ hl,
                     __half* __restrict__ hf,
                     const float* __restrict__ w, const float* __restrict__ b,
                     int residual)
{
    const int token = blockIdx.x;
    const size_t base = (size_t)token * KD;
    const int tid = threadIdx.x;
    float x0 = src[base + tid];
    float x1 = src[base + tid + 256];
    if (residual) { x0 += h[base + tid]; x1 += h[base + tid + 256]; }
    __shared__ float s1[256], s2[256];
    s1[tid] = x0 + x1;
    s2[tid] = x0 * x0 + x1 * x1;
    __syncthreads();
    for (int o = 128; o; o >>= 1) {
        if (tid < o) { s1[tid] += s1[tid + o]; s2[tid] += s2[tid + o]; }
        __syncthreads();
    }
    const float mean = s1[0] * (1.f / KD);
    const float var  = s2[0] * (1.f / KD) - mean * mean;
    const float r = rsqrtf(var + 1e-5f);
    const float y0 = (x0 - mean) * r * w[tid]       + b[tid];
    const float y1 = (x1 - mean) * r * w[tid + 256] + b[tid + 256];
    h[base + tid]       = y0;
    h[base + tid + 256] = y1;
    splitw(y0, hh + base + tid,       hl + base + tid);
    splitw(y1, hh + base + tid + 256, hl + base + tid + 256);
    hf[base + tid]       = __float2half(y0);
    hf[base + tid + 256] = __float2half(y1);
}

// ---------------------------------------------------------------------------
// Host-side launcher
// ---------------------------------------------------------------------------
struct GemmArgs {
    const void *Ah, *Al, *Bh, *Bl;
    const float* bias;
    float* C;
    void *Ch, *Cl;
    int M, N, K, lda, ldb, ldc;
    long aO, aI, bO, bI, cO, cI;
    int zdiv, batches, causal;
};

template<int EPI, int OUT, int DT>
static void launch_gemm(const GemmArgs& a)
{
    static bool attr_set = false;
    if (!attr_set) {
        cudaFuncSetAttribute(gemm_ps<EPI, OUT, DT>,
                             cudaFuncAttributeMaxDynamicSharedMemorySize, GEMM_SMEM);
        attr_set = true;
    }
    dim3 grid(a.N / 128, a.M / 128, a.batches), block(256);
    gemm_ps<EPI, OUT, DT><<<grid, block, GEMM_SMEM>>>(
        (const __nv_bfloat16*)a.Ah, (const __nv_bfloat16*)a.Al,
        (const __nv_bfloat16*)a.Bh, (const __nv_bfloat16*)a.Bl,
        a.bias, a.C, (__nv_bfloat16*)a.Ch, (__nv_bfloat16*)a.Cl,
        a.M, a.N, a.K, a.lda, a.ldb, a.ldc,
        a.aO, a.aI, a.bO, a.bI, a.cO, a.cI, a.zdiv, a.causal);
}

extern "C" void kernel_launch(void* const* d_in, const int* in_sizes, int n_in,
                              void* d_out, int out_size)
{
    const int*   x        = (const int*)  d_in[0];
    const float* embed_W  = (const float*)d_in[1];
    const float* Wq       = (const float*)d_in[2];
    const float* Wk       = (const float*)d_in[3];
    const float* Wv       = (const float*)d_in[4];
    const float* Wu       = (const float*)d_in[5];
    const float* bu       = (const float*)d_in[6];
    const float* W1       = (const float*)d_in[7];
    const float* b1       = (const float*)d_in[8];
    const float* W2       = (const float*)d_in[9];
    const float* b2       = (const float*)d_in[10];
    const float* ln1_w    = (const float*)d_in[11];
    const float* ln1_b    = (const float*)d_in[12];
    const float* ln2_w    = (const float*)d_in[13];
    const float* ln2_b    = (const float*)d_in[14];
    const float* lnf_w    = (const float*)d_in[15];
    const float* lnf_b    = (const float*)d_in[16];
    const float* unembedW = (const float*)d_in[17];
    const float* unembedB = (const float*)d_in[18];
    float* out = (float*)d_out;

    float *h, *att, *tmp;
    __nv_bfloat16 *hsh, *hsl, *wth, *wtl, *ysh, *ysl, *fsh, *fsl;
    __half *hf, *qv, *vt, *as;
    cudaGetSymbolAddress((void**)&h,   g_h);
    cudaGetSymbolAddress((void**)&att, g_att);
    cudaGetSymbolAddress((void**)&tmp, g_tmp);
    cudaGetSymbolAddress((void**)&hsh, g_hs_h); cudaGetSymbolAddress((void**)&hsl, g_hs_l);
    cudaGetSymbolAddress((void**)&hf,  g_hf);
    cudaGetSymbolAddress((void**)&wth, g_wt_h); cudaGetSymbolAddress((void**)&wtl, g_wt_l);
    cudaGetSymbolAddress((void**)&qv,  g_qkv);
    cudaGetSymbolAddress((void**)&vt,  g_vt);
    cudaGetSymbolAddress((void**)&as,  g_as);
    cudaGetSymbolAddress((void**)&ysh, g_ys_h); cudaGetSymbolAddress((void**)&ysl, g_ys_l);
    cudaGetSymbolAddress((void**)&fsh, g_fs_h); cudaGetSymbolAddress((void**)&fsl, g_fs_l);

    embed_k<<<MTOK, 256>>>(x, embed_W, h, hsh, hsl, hf);

    const long atI = (long)SEQ * SEQ;          // 262144
    const long atO = (long)HEADS * atI;

    for (int i = 0; i < NBLK; i++) {
        const float* Wq_i = Wq + (size_t)i * KD * HK;
        const float* Wk_i = Wk + (size_t)i * KD * HK;
        const float* Wv_i = Wv + (size_t)i * KD * HK;
        const float* Wu_i = Wu + (size_t)i * HK * KD;
        const float* bu_i = bu + (size_t)i * KD;
        const float* W1_i = W1 + (size_t)i * KD * FF;
        const float* b1_i = b1 + (size_t)i * FF;
        const float* W2_i = W2 + (size_t)i * FF * KD;
        const float* b2_i = b2 + (size_t)i * KD;

        // fused QKV (fp16 single): weights -> fp16 [12288][512], wide GEMM
        wconv3h<<<dim3(KD/32, HK/32, 3), dim3(32,8)>>>(Wq_i, Wk_i, Wv_i, (__half*)wth);
        { GemmArgs a = {hf, nullptr, wth, nullptr, nullptr, nullptr, qv, nullptr,
                        MTOK, QKVN, KD, KD, KD, QKVN, 0,0,0,0,0,0, 1, 1, 0};
          launch_gemm<0,2,1>(a); }

        // scores = Q @ K^T (fp16); skip upper-triangle tiles
        { GemmArgs a = {qv, nullptr, qv + HK, nullptr, nullptr, att, nullptr, nullptr,
                        SEQ, SEQ, KD, QKVN, QKVN, SEQ,
                        (long)SEQ*QKVN, (long)KD, (long)SEQ*QKVN, (long)KD,
                        atO, atI, HEADS, NBH, 1};
          launch_gemm<0,0,1>(a); }

        softmax_k<<<dim3(SEQ, NBH), 256>>>(att, as);
        vconvh<<<dim3(16,16,NBH), dim3(32,8)>>>(qv, vt);

        // y = att @ V (fp16 in, split bf16 out); truncate K per tile row
        { GemmArgs a = {as, nullptr, vt, nullptr, nullptr, nullptr, ysh, ysl,
                        SEQ, KD, SEQ, SEQ, SEQ, HK,
                        atO, atI, atO, atI,
                        (long)SEQ*HK, (long)KD, HEADS, NBH, 2};
          launch_gemm<0,1,1>(a); }

        // proj (bf16x3, split-K=4) -> partials in att -> reduce+bias
        wconv<<<dim3(HK/32, KD/32), dim3(32,8)>>>(Wu_i, wth, wtl, HK, KD);
        { GemmArgs a = {ysh, ysl, wth, wtl, nullptr, att, nullptr, nullptr,
                        MTOK, KD, 1024, HK, HK, KD,
                        1024, 0, 1024, 0, (long)MTOK*KD, 0, 1, 4, 0};
          launch_gemm<0,0,0>(a); }
        reduce_k<<<(MTOK*KD/4 + 255)/256, 256>>>(att, bu_i, tmp, KD, MTOK*KD/4);

        ln_k<<<MTOK, 256>>>(tmp, h, hsh, hsl, hf,
                            ln1_w + (size_t)i * KD, ln1_b + (size_t)i * KD, 1);

        // ff = gelu(h @ W1 + b1) (bf16x3, split output)
        wconv<<<dim3(KD/32, FF/32), dim3(32,8)>>>(W1_i, wth, wtl, KD, FF);
        { GemmArgs a = {hsh, hsl, wth, wtl, b1_i, nullptr, fsh, fsl,
                        MTOK, FF, KD, KD, KD, FF, 0,0,0,0,0,0, 1, 1, 0};
          launch_gemm<2,1,0>(a); }

        // tmp = ff @ W2 + b2 (bf16x3, split-K=4) -> partials -> reduce
        wconv<<<dim3(FF/32, KD/32), dim3(32,8)>>>(W2_i, wth, wtl, FF, KD);
        { GemmArgs a = {fsh, fsl, wth, wtl, nullptr, att, nullptr, nullptr,
                        MTOK, KD, 512, FF, FF, KD,
                        512, 0, 512, 0, (long)MTOK*KD, 0, 1, 4, 0};
          launch_gemm<0,0,0>(a); }
        reduce_k<<<(MTOK*KD/4 + 255)/256, 256>>>(att, b2_i, tmp, KD, MTOK*KD/4);

        ln_k<<<MTOK, 256>>>(tmp, h, hsh, hsl, hf,
                            ln2_w + (size_t)i * KD, ln2_b + (size_t)i * KD, 1);
    }

    ln_k<<<MTOK, 256>>>(h, h, hsh, hsl, hf, lnf_w, lnf_b, 0);

    // unembed (fp16 single): weights -> fp16 [VOCAB][KD]
    wconvh<<<dim3(KD/32, VOCAB/32), dim3(32,8)>>>(unembedW, (__half*)wth, KD, VOCAB);
    { GemmArgs a = {hf, nullptr, wth, nullptr, unembedB, out, nullptr, nullptr,
                    MTOK, VOCAB, KD, KD, KD, VOCAB, 0,0,0,0,0,0, 1, 1, 0};
      launch_gemm<1,0,1>(a); }
}

// round 14
// speedup vs baseline: 2.7995x; 1.3096x over previous
#include <cuda_runtime.h>
#include <cuda_bf16.h>
#include <cuda_fp16.h>
#include <math.h>

// ---------------------------------------------------------------------------
// GPT forward. All-fp16 tensor-core GEMMs (fp32 accumulate), fp32 elementwise.
// B=4, T=512, K=512, H=8, NB=4, VOCAB=32000. M = B*T = 2048 tokens.
//
// R14: every GEMM is fp16 single-pass mma.m16n8k16 (fp32 acc). LayerNorm
// re-normalizes each block; split-K reductions in fp32. Causal skip/truncate,
// fused QKV, split-K skinny GEMMs as before.
// ---------------------------------------------------------------------------

#define BATCH 4
#define SEQ   512
#define KD    512
#define HEADS 8
#define NBLK  4
#define VOCAB 32000
#define MTOK  (BATCH*SEQ)        // 2048
#define HK    (HEADS*KD)         // 4096
#define QKVN  (3*HK)             // 12288
#define FF    (4*KD)             // 2048
#define NBH   (BATCH*HEADS)      // 32

// fp32 scratch
__device__ float g_h  [MTOK*KD];
__device__ float g_att[NBH*SEQ*SEQ];      // scores; reused as split-K partials
__device__ float g_tmp[MTOK*KD];
// fp16 scratch
__device__ __align__(256) __half g_hf  [MTOK*KD];            // fp16 hidden
__device__ __align__(256) __half g_wt  [(size_t)VOCAB*KD];   // fp16 weights (transposed)
__device__ __align__(256) __half g_qkv [(size_t)MTOK*QKVN];  // fp16 QKV
__device__ __align__(256) __half g_vt  [MTOK*HK];            // fp16 V^T
__device__ __align__(256) __half g_as  [NBH*SEQ*SEQ];        // fp16 att
__device__ __align__(256) __half g_yf  [MTOK*HK];            // fp16 attention out
__device__ __align__(256) __half g_ff  [MTOK*FF];            // fp16 gelu out

// ---------------------------------------------------------------------------
// helpers
// ---------------------------------------------------------------------------
__device__ __forceinline__ unsigned smem_u32(const void* p) {
    unsigned r;
    asm("{ .reg .u64 t; cvta.to.shared.u64 t, %1; cvt.u32.u64 %0, t; }"
        : "=r"(r) : "l"(p));
    return r;
}
__device__ __forceinline__ void cp16(unsigned dst, const void* src) {
    asm volatile("cp.async.cg.shared.global [%0], [%1], 16;" :: "r"(dst), "l"(src));
}
#define CP_COMMIT() asm volatile("cp.async.commit_group;" ::: "memory")
#define CP_WAIT1()  asm volatile("cp.async.wait_group 1;" ::: "memory")

__device__ __forceinline__ void ldsm4(unsigned addr, unsigned& r0, unsigned& r1,
                                      unsigned& r2, unsigned& r3) {
    asm volatile("ldmatrix.sync.aligned.m8n8.x4.shared.b16 {%0,%1,%2,%3}, [%4];"
                 : "=r"(r0), "=r"(r1), "=r"(r2), "=r"(r3) : "r"(addr));
}
__device__ __forceinline__ void ldsm2(unsigned addr, unsigned& r0, unsigned& r1) {
    asm volatile("ldmatrix.sync.aligned.m8n8.x2.shared.b16 {%0,%1}, [%2];"
                 : "=r"(r0), "=r"(r1) : "r"(addr));
}
__device__ __forceinline__ void mma_f16(float* c, const unsigned* a, const unsigned* b) {
    asm volatile(
        "mma.sync.aligned.m16n8k16.row.col.f32.f16.f16.f32 "
        "{%0,%1,%2,%3},{%4,%5,%6,%7},{%8,%9},{%0,%1,%2,%3};"
        : "+f"(c[0]), "+f"(c[1]), "+f"(c[2]), "+f"(c[3])
        : "r"(a[0]), "r"(a[1]), "r"(a[2]), "r"(a[3]), "r"(b[0]), "r"(b[1]));
}

// SMEM stage layout (uint32 units): [A 2048 | B 2048] (fp16 operands only)
#define ST_U32 4096
#define A_OFF  0
#define B_OFF  2048
#define NSTAGE 3
#define GEMM_SMEM (NSTAGE*ST_U32*4)   // 49152 bytes

// ---------------------------------------------------------------------------
// Pipelined fp16 GEMM.  A: [M][K] fp16, lda.  B: [N][K] fp16, ldb.
// C = A * B^T.  EPI: 0 none, 1 +bias, 2 gelu(x+bias).
// OUT: 0 fp32 C; 2 fp16 Ch.
// causal: 0 none, 1 tile-skip (bx>by), 2 K-trunc to (by+1)*128.
// Batched / split-K via blockIdx.z. M%128==0, N%128==0, K%32==0.
// ---------------------------------------------------------------------------
template<int EPI, int OUT>
__global__ __launch_bounds__(256, 2)
void gemm_f16(const __half* __restrict__ A, const __half* __restrict__ B,
              const float* __restrict__ bias,
              float* __restrict__ C, __half* __restrict__ Ch,
              int M, int N, int K, int lda, int ldb, int ldc,
              long aO, long aI, long bO, long bI, long cO, long cI, int zdiv,
              int causal)
{
    extern __shared__ unsigned sm[];
    const unsigned base32 = smem_u32(sm);

    const int bx = blockIdx.x, by = blockIdx.y;
    if (causal == 1 && bx > by) return;
    if (causal == 2) K = min(K, (by + 1) * 128);

    const int z  = blockIdx.z;
    const int zb = z / zdiv, zh = z - zb * zdiv;
    const size_t aoff = (size_t)zb * aO + (size_t)zh * aI;
    const size_t boff = (size_t)zb * bO + (size_t)zh * bI;
    const size_t coff = (size_t)zb * cO + (size_t)zh * cI;
    A += aoff; B += boff;

    const int tid  = threadIdx.x;
    const int lane = tid & 31;
    const int warp = tid >> 5;
    const int g    = lane >> 2;
    const int tc   = lane & 3;
    const int wm   = (warp >> 2) * 64;
    const int wn   = (warp & 3) * 32;

    const int crow = tid >> 1;
    const int cj   = (tid & 1) * 2;
    const __half* pA = A + (size_t)(by * 128 + crow) * lda + cj * 8;
    const __half* pB = B + (size_t)(bx * 128 + crow) * ldb + cj * 8;
    const int csw = (crow & 6) << 1;
    const int cs0 = crow * 16 + ((4 * cj)     ^ csw);
    const int cs1 = crow * 16 + ((4 * cj + 4) ^ csw);

    int idxA[4][2], idxB[4][2];
    {
        const int rowA = wm + (lane & 15);
        const int cgA0 = (lane >> 4) << 2;
        const int rowB = wn + (lane & 7);
        const int cgB0 = ((lane >> 3) & 1) << 2;
        #pragma unroll
        for (int mf = 0; mf < 4; mf++) {
            const int r = rowA + mf * 16;
            idxA[mf][0] = r * 16 + ((cgA0)     ^ ((r & 6) << 1));
            idxA[mf][1] = r * 16 + ((cgA0 + 8) ^ ((r & 6) << 1));
        }
        #pragma unroll
        for (int nf = 0; nf < 4; nf++) {
            const int r = rowB + nf * 8;
            idxB[nf][0] = r * 16 + ((cgB0)     ^ ((r & 6) << 1));
            idxB[nf][1] = r * 16 + ((cgB0 + 8) ^ ((r & 6) << 1));
        }
    }

    float acc[4][4][4];
    #pragma unroll
    for (int i = 0; i < 4; i++)
        #pragma unroll
        for (int j = 0; j < 4; j++)
            #pragma unroll
            for (int r = 0; r < 4; r++) acc[i][j][r] = 0.f;

    auto ISSUE = [&](int buf, int k0) {
        const unsigned sb = base32 + buf * (ST_U32 * 4);
        cp16(sb + (A_OFF + cs0) * 4, pA + k0);
        cp16(sb + (A_OFF + cs1) * 4, pA + k0 + 8);
        cp16(sb + (B_OFF + cs0) * 4, pB + k0);
        cp16(sb + (B_OFF + cs1) * 4, pB + k0 + 8);
    };

    const int nc = K >> 5;

    ISSUE(0, 0);  CP_COMMIT();
    if (nc > 1) ISSUE(1, 32);
    CP_COMMIT();

    for (int i = 0; i < nc; i++) {
        CP_WAIT1();
        __syncthreads();

        if (i + 2 < nc) ISSUE((i + 2) % NSTAGE, (i + 2) * 32);
        CP_COMMIT();

        const unsigned stb = base32 + (i % NSTAGE) * (ST_U32 * 4);
        #pragma unroll
        for (int kpb = 0; kpb < 2; kpb++) {
            unsigned Bf[4][2];
            #pragma unroll
            for (int nf = 0; nf < 4; nf++)
                ldsm2(stb + (B_OFF + idxB[nf][kpb]) * 4, Bf[nf][0], Bf[nf][1]);
            #pragma unroll
            for (int mf = 0; mf < 4; mf++) {
                unsigned Aa[4];
                ldsm4(stb + (A_OFF + idxA[mf][kpb]) * 4, Aa[0], Aa[1], Aa[2], Aa[3]);
                #pragma unroll
                for (int nf = 0; nf < 4; nf++)
                    mma_f16(acc[mf][nf], Aa, Bf[nf]);
            }
        }
    }

    // ---- epilogue ----
    #pragma unroll
    for (int mf = 0; mf < 4; mf++) {
        const int r0 = by * 128 + wm + mf * 16 + g;
        #pragma unroll
        for (int nf = 0; nf < 4; nf++) {
            const int col = bx * 128 + wn + nf * 8 + tc * 2;
            float c0 = acc[mf][nf][0], c1 = acc[mf][nf][1];
            float c2 = acc[mf][nf][2], c3 = acc[mf][nf][3];
            if (EPI >= 1) {
                const float b0v = bias[col], b1v = bias[col + 1];
                c0 += b0v; c1 += b1v; c2 += b0v; c3 += b1v;
            }
            if (EPI == 2) {
                c0 = 0.5f * c0 * (1.0f + erff(c0 * 0.7071067811865475f));
                c1 = 0.5f * c1 * (1.0f + erff(c1 * 0.7071067811865475f));
                c2 = 0.5f * c2 * (1.0f + erff(c2 * 0.7071067811865475f));
                c3 = 0.5f * c3 * (1.0f + erff(c3 * 0.7071067811865475f));
            }
            if (OUT == 0) {
                *(float2*)&C[coff + (size_t)r0 * ldc + col]       = make_float2(c0, c1);
                *(float2*)&C[coff + (size_t)(r0 + 8) * ldc + col] = make_float2(c2, c3);
            } else {
                *(__half2*)&Ch[coff + (size_t)r0 * ldc + col]       = __floats2half2_rn(c0, c1);
                *(__half2*)&Ch[coff + (size_t)(r0 + 8) * ldc + col] = __floats2half2_rn(c2, c3);
            }
        }
    }
}

// ---------------------------------------------------------------------------
// Split-K reduction: out = bias + sum of 4 partial planes.
// ---------------------------------------------------------------------------
__global__ void reduce_k(const float* __restrict__ P, const float* __restrict__ bias,
                         float* __restrict__ out, int n, int total4)
{
    const int i = blockIdx.x * 256 + threadIdx.x;
    if (i >= total4) return;
    float4 a = ((const float4*)P)[i];
    #pragma unroll
    for (int s = 1; s < 4; s++) {
        float4 b = ((const float4*)P)[i + (size_t)s * total4];
        a.x += b.x; a.y += b.y; a.z += b.z; a.w += b.w;
    }
    const int c = (i * 4) & (n - 1);
    a.x += bias[c]; a.y += bias[c + 1]; a.z += bias[c + 2]; a.w += bias[c + 3];
    ((float4*)out)[i] = a;
}

// ---------------------------------------------------------------------------
// Weight transpose, fp16: src fp32 [K][N] -> dst fp16 [N][K].
// ---------------------------------------------------------------------------
__global__ void wconvh(const float* __restrict__ src, __half* __restrict__ dh,
                       int K, int N)
{
    __shared__ float t[32][33];
    const int k0 = blockIdx.x * 32, n0 = blockIdx.y * 32;
    const int tx = threadIdx.x, ty = threadIdx.y;
    #pragma unroll
    for (int r = 0; r < 4; r++)
        t[ty + r * 8][tx] = src[(size_t)(k0 + ty + r * 8) * N + n0 + tx];
    __syncthreads();
    #pragma unroll
    for (int r = 0; r < 4; r++)
        dh[(size_t)(n0 + ty + r * 8) * K + k0 + tx] = __float2half(t[tx][ty + r * 8]);
}

// Fused Wq/Wk/Wv transpose -> fp16 [QKVN][KD]. grid z picks src.
__global__ void wconv3h(const float* __restrict__ s0, const float* __restrict__ s1,
                        const float* __restrict__ s2, __half* __restrict__ dh)
{
    __shared__ float t[32][33];
    const float* src = (blockIdx.z == 0) ? s0 : (blockIdx.z == 1 ? s1 : s2);
    const int k0 = blockIdx.x * 32, n0 = blockIdx.y * 32;
    const int tx = threadIdx.x, ty = threadIdx.y;
    #pragma unroll
    for (int r = 0; r < 4; r++)
        t[ty + r * 8][tx] = src[(size_t)(k0 + ty + r * 8) * HK + n0 + tx];
    __syncthreads();
    const size_t rowoff = (size_t)blockIdx.z * HK;
    #pragma unroll
    for (int r = 0; r < 4; r++)
        dh[(rowoff + n0 + ty + r * 8) * KD + k0 + tx] = __float2half(t[tx][ty + r * 8]);
}

// ---------------------------------------------------------------------------
// V transpose per head from fp16 QKV buffer -> fp16 [(b*8+h)*512+d][t].
// ---------------------------------------------------------------------------
__global__ void vconvh(const __half* __restrict__ qv, __half* __restrict__ dh)
{
    __shared__ __half t[32][33];
    const int z = blockIdx.z, b = z >> 3, h = z & 7;
    const int t0 = blockIdx.x * 32, d0 = blockIdx.y * 32;
    const int tx = threadIdx.x, ty = threadIdx.y;
    #pragma unroll
    for (int r = 0; r < 4; r++) {
        const size_t si = (size_t)(b * SEQ + t0 + ty + r * 8) * QKVN
                        + 2 * HK + h * KD + d0 + tx;
        t[ty + r * 8][tx] = qv[si];
    }
    __syncthreads();
    #pragma unroll
    for (int r = 0; r < 4; r++) {
        const size_t o = ((size_t)z * KD + d0 + ty + r * 8) * SEQ + t0 + tx;
        dh[o] = t[tx][ty + r * 8];
    }
}

// ---------------------------------------------------------------------------
// Embedding + positional encoding. Writes fp32 h and fp16 hf.
// ---------------------------------------------------------------------------
__global__ void embed_k(const int* __restrict__ x, const float* __restrict__ W,
                        float* __restrict__ h, __half* __restrict__ hf)
{
    const int token = blockIdx.x;
    const int t  = token & (SEQ - 1);
    const int id = x[token];
    const int tid = threadIdx.x;
    #pragma unroll
    for (int u = 0; u < 2; u++) {
        const int c = tid + u * 256;
        const int j = c >> 1;
        const float ang = (float)t * expf(-(float)j * 0.07195578415606394f);
        const float p = (c & 1) ? cosf(ang) : sinf(ang);
        const float val = W[(size_t)id * KD + c] + p;
        const size_t o = (size_t)token * KD + c;
        h[o] = val;
        hf[o] = __float2half(val);
    }
}

// ---------------------------------------------------------------------------
// Causal softmax (scale folded), writes fp16 att. grid(SEQ, 32), 256 thr.
// ---------------------------------------------------------------------------
__global__ void softmax_k(const float* __restrict__ att, __half* __restrict__ oh)
{
    const int q  = blockIdx.x;
    const int bh = blockIdx.y;
    const size_t base = ((size_t)bh * SEQ + q) * SEQ;
    const int tid = threadIdx.x;
    const float scale = 0.04419417382415922f;  // 1/sqrt(512)
    __shared__ float red[256];

    const float s0 = (tid       <= q) ? att[base + tid]       * scale : -3.4e38f;
    const float s1 = (tid + 256 <= q) ? att[base + tid + 256] * scale : -3.4e38f;
    red[tid] = fmaxf(s0, s1);
    __syncthreads();
    for (int o = 128; o; o >>= 1) {
        if (tid < o) red[tid] = fmaxf(red[tid], red[tid + o]);
        __syncthreads();
    }
    const float m = red[0];
    __syncthreads();
    const float v0 = (tid       <= q) ? expf(s0 - m) : 0.f;
    const float v1 = (tid + 256 <= q) ? expf(s1 - m) : 0.f;
    red[tid] = v0 + v1;
    __syncthreads();
    for (int o = 128; o; o >>= 1) {
        if (tid < o) red[tid] += red[tid + o];
        __syncthreads();
    }
    const float inv = 1.0f / red[0];
    oh[base + tid]       = __float2half(v0 * inv);
    oh[base + tid + 256] = __float2half(v1 * inv);
}

// ---------------------------------------------------------------------------
// (optional residual) + LayerNorm. Writes fp32 h and fp16 hf.
// ---------------------------------------------------------------------------
__global__ void ln_k(const float* __restrict__ src, float* __restrict__ h,
                     __half* __restrict__ hf,
                     const float* __restrict__ w, const float* __restrict__ b,
                     int residual)
{
    const int token = blockIdx.x;
    const size_t base = (size_t)token * KD;
    const int tid = threadIdx.x;
    float x0 = src[base + tid];
    float x1 = src[base + tid + 256];
    if (residual) { x0 += h[base + tid]; x1 += h[base + tid + 256]; }
    __shared__ float s1[256], s2[256];
    s1[tid] = x0 + x1;
    s2[tid] = x0 * x0 + x1 * x1;
    __syncthreads();
    for (int o = 128; o; o >>= 1) {
        if (tid < o) { s1[tid] += s1[tid + o]; s2[tid] += s2[tid + o]; }
        __syncthreads();
    }
    const float mean = s1[0] * (1.f / KD);
    const float var  = s2[0] * (1.f / KD) - mean * mean;
    const float r = rsqrtf(var + 1e-5f);
    const float y0 = (x0 - mean) * r * w[tid]       + b[tid];
    const float y1 = (x1 - mean) * r * w[tid + 256] + b[tid + 256];
    h[base + tid]       = y0;
    h[base + tid + 256] = y1;
    hf[base + tid]       = __float2half(y0);
    hf[base + tid + 256] = __float2half(y1);
}

// ---------------------------------------------------------------------------
// Host-side launcher
// ---------------------------------------------------------------------------
struct GemmArgs {
    const __half *A, *B;
    const float* bias;
    float* C;
    __half* Ch;
    int M, N, K, lda, ldb, ldc;
    long aO, aI, bO, bI, cO, cI;
    int zdiv, batches, causal;
};

template<int EPI, int OUT>
static void launch_gemm(const GemmArgs& a)
{
    static bool attr_set = false;
    if (!attr_set) {
        cudaFuncSetAttribute(gemm_f16<EPI, OUT>,
                             cudaFuncAttributeMaxDynamicSharedMemorySize, GEMM_SMEM);
        attr_set = true;
    }
    dim3 grid(a.N / 128, a.M / 128, a.batches), block(256);
    gemm_f16<EPI, OUT><<<grid, block, GEMM_SMEM>>>(
        a.A, a.B, a.bias, a.C, a.Ch,
        a.M, a.N, a.K, a.lda, a.ldb, a.ldc,
        a.aO, a.aI, a.bO, a.bI, a.cO, a.cI, a.zdiv, a.causal);
}

extern "C" void kernel_launch(void* const* d_in, const int* in_sizes, int n_in,
                              void* d_out, int out_size)
{
    const int*   x        = (const int*)  d_in[0];
    const float* embed_W  = (const float*)d_in[1];
    const float* Wq       = (const float*)d_in[2];
    const float* Wk       = (const float*)d_in[3];
    const float* Wv       = (const float*)d_in[4];
    const float* Wu       = (const float*)d_in[5];
    const float* bu       = (const float*)d_in[6];
    const float* W1       = (const float*)d_in[7];
    const float* b1       = (const float*)d_in[8];
    const float* W2       = (const float*)d_in[9];
    const float* b2       = (const float*)d_in[10];
    const float* ln1_w    = (const float*)d_in[11];
    const float* ln1_b    = (const float*)d_in[12];
    const float* ln2_w    = (const float*)d_in[13];
    const float* ln2_b    = (const float*)d_in[14];
    const float* lnf_w    = (const float*)d_in[15];
    const float* lnf_b    = (const float*)d_in[16];
    const float* unembedW = (const float*)d_in[17];
    const float* unembedB = (const float*)d_in[18];
    float* out = (float*)d_out;

    float *h, *att, *tmp;
    __half *hf, *wt, *qv, *vt, *as, *yf, *ff;
    cudaGetSymbolAddress((void**)&h,   g_h);
    cudaGetSymbolAddress((void**)&att, g_att);
    cudaGetSymbolAddress((void**)&tmp, g_tmp);
    cudaGetSymbolAddress((void**)&hf,  g_hf);
    cudaGetSymbolAddress((void**)&wt,  g_wt);
    cudaGetSymbolAddress((void**)&qv,  g_qkv);
    cudaGetSymbolAddress((void**)&vt,  g_vt);
    cudaGetSymbolAddress((void**)&as,  g_as);
    cudaGetSymbolAddress((void**)&yf,  g_yf);
    cudaGetSymbolAddress((void**)&ff,  g_ff);

    embed_k<<<MTOK, 256>>>(x, embed_W, h, hf);

    const long atI = (long)SEQ * SEQ;          // 262144
    const long atO = (long)HEADS * atI;

    for (int i = 0; i < NBLK; i++) {
        const float* Wq_i = Wq + (size_t)i * KD * HK;
        const float* Wk_i = Wk + (size_t)i * KD * HK;
        const float* Wv_i = Wv + (size_t)i * KD * HK;
        const float* Wu_i = Wu + (size_t)i * HK * KD;
        const float* bu_i = bu + (size_t)i * KD;
        const float* W1_i = W1 + (size_t)i * KD * FF;
        const float* b1_i = b1 + (size_t)i * FF;
        const float* W2_i = W2 + (size_t)i * FF * KD;
        const float* b2_i = b2 + (size_t)i * KD;

        // fused QKV
        wconv3h<<<dim3(KD/32, HK/32, 3), dim3(32,8)>>>(Wq_i, Wk_i, Wv_i, wt);
        { GemmArgs a = {hf, wt, nullptr, nullptr, qv,
                        MTOK, QKVN, KD, KD, KD, QKVN, 0,0,0,0,0,0, 1, 1, 0};
          launch_gemm<0,2>(a); }

        // scores = Q @ K^T; skip upper-triangle tiles
        { GemmArgs a = {qv, qv + HK, nullptr, att, nullptr,
                        SEQ, SEQ, KD, QKVN, QKVN, SEQ,
                        (long)SEQ*QKVN, (long)KD, (long)SEQ*QKVN, (long)KD,
                        atO, atI, HEADS, NBH, 1};
          launch_gemm<0,0>(a); }

        softmax_k<<<dim3(SEQ, NBH), 256>>>(att, as);
        vconvh<<<dim3(16,16,NBH), dim3(32,8)>>>(qv, vt);

        // y = att @ V; truncate K per tile row
        { GemmArgs a = {as, vt, nullptr, nullptr, yf,
                        SEQ, KD, SEQ, SEQ, SEQ, HK,
                        atO, atI, atO, atI,
                        (long)SEQ*HK, (long)KD, HEADS, NBH, 2};
          launch_gemm<0,2>(a); }

        // proj: split-K=4 -> partials in att -> reduce+bias
        wconvh<<<dim3(HK/32, KD/32), dim3(32,8)>>>(Wu_i, wt, HK, KD);
        { GemmArgs a = {yf, wt, nullptr, att, nullptr,
                        MTOK, KD, 1024, HK, HK, KD,
                        1024, 0, 1024, 0, (long)MTOK*KD, 0, 1, 4, 0};
          launch_gemm<0,0>(a); }
        reduce_k<<<(MTOK*KD/4 + 255)/256, 256>>>(att, bu_i, tmp, KD, MTOK*KD/4);

        ln_k<<<MTOK, 256>>>(tmp, h, hf,
                            ln1_w + (size_t)i * KD, ln1_b + (size_t)i * KD, 1);

        // ff = gelu(h @ W1 + b1) -> fp16
        wconvh<<<dim3(KD/32, FF/32), dim3(32,8)>>>(W1_i, wt, KD, FF);
        { GemmArgs a = {hf, wt, b1_i, nullptr, ff,
                        MTOK, FF, KD, KD, KD, FF, 0,0,0,0,0,0, 1, 1, 0};
          launch_gemm<2,2>(a); }

        // tmp = ff @ W2 + b2: split-K=4 -> partials -> reduce
        wconvh<<<dim3(FF/32, KD/32), dim3(32,8)>>>(W2_i, wt, FF, KD);
        { GemmArgs a = {ff, wt, nullptr, att, nullptr,
                        MTOK, KD, 512, FF, FF, KD,
                        512, 0, 512, 0, (long)MTOK*KD, 0, 1, 4, 0};
          launch_gemm<0,0>(a); }
        reduce_k<<<(MTOK*KD/4 + 255)/256, 256>>>(att, b2_i, tmp, KD, MTOK*KD/4);

        ln_k<<<MTOK, 256>>>(tmp, h, hf,
                            ln2_w + (size_t)i * KD, ln2_b + (size_t)i * KD, 1);
    }

    ln_k<<<MTOK, 256>>>(h, h, hf, lnf_w, lnf_b, 0);

    // unembed
    wconvh<<<dim3(KD/32, VOCAB/32), dim3(32,8)>>>(unembedW, wt, KD, VOCAB);
    { GemmArgs a = {hf, wt, unembedB, out, nullptr,
                    MTOK, VOCAB, KD, KD, KD, VOCAB, 0,0,0,0,0,0, 1, 1, 0};
      launch_gemm<1,0>(a); }
}